// round 4
// baseline (speedup 1.0000x reference)
#include <cuda_runtime.h>
#include <cstdint>

// Problem shape (fixed by the dataset instance)
#define BB   2
#define HH   32
#define SS   4096
#define DD   128
#define BLK  512
#define NB   (SS / BLK)          // 8
#define NCTA (BB * HH * NB)      // 512
#define NT   256
#define EPS_F 1e-6f

// Smem strides chosen for conflict-free mma fragment loads:
//  A-fragment loads (stride SPAD=132): bank = (4t + g) -> 32 distinct
//  B-fragment loads (stride VPAD=136): bank = (8t + g) -> 32 distinct
#define SPAD 132
#define VPAD 136

// Shared memory layout (floats)
#define SDM_OFF   0                        // S_dm: 128 x 136        (17408)
#define STAGE_OFF (DD * VPAD)              // stage: 64 x 132 region  (8448)
#define Z_OFF     (STAGE_OFF + 64 * SPAD)  // Z[128]
#define DEN_OFF   (Z_OFF + DD)             // den[64]
#define SMEM_FLOATS (DEN_OFF + 64)
#define SMEM_BYTES  (SMEM_FLOATS * 4)      // 104192 B -> 2 CTAs/SM

__device__ __forceinline__ float phi_elu1(float y) {
    return y > 0.0f ? y + 1.0f : __expf(y);
}

__device__ __forceinline__ uint32_t f2tf(float x) {
    uint32_t u;
    asm("cvt.rna.tf32.f32 %0, %1;" : "=r"(u) : "f"(x));
    return u;
}

__device__ __forceinline__ void mma_tf32(float* c, const uint32_t* a, const uint32_t* b) {
    asm volatile(
        "mma.sync.aligned.m16n8k8.row.col.f32.tf32.tf32.f32 "
        "{%0,%1,%2,%3}, {%4,%5,%6,%7}, {%8,%9}, {%0,%1,%2,%3};\n"
        : "+f"(c[0]), "+f"(c[1]), "+f"(c[2]), "+f"(c[3])
        : "r"(a[0]), "r"(a[1]), "r"(a[2]), "r"(a[3]), "r"(b[0]), "r"(b[1]));
}

extern "C" __global__ void __launch_bounds__(NT, 2)
lin_attn_tc(const float* __restrict__ q,
            const float* __restrict__ k,
            const float* __restrict__ v,
            const float* __restrict__ sc,
            const float* __restrict__ bi,
            float* __restrict__ out)
{
    extern __shared__ float sm[];
    float* Sdm   = sm + SDM_OFF;           // [128][VPAD]
    float* stage = sm + STAGE_OFF;         // phase1: phiK[16][SPAD] + V[16][VPAD]; phase2: phiQ[64][SPAD]
    float* Zsm   = sm + Z_OFF;             // [128]
    float* den   = sm + DEN_OFF;           // [64]

    float* phik_s = stage;                 // 16 x SPAD
    float* v_s    = stage + 16 * SPAD;     // 16 x VPAD

    const int tid  = threadIdx.x;
    const int lane = tid & 31;
    const int w    = tid >> 5;             // warp 0..7
    const int g    = lane >> 2;            // 0..7
    const int t    = lane & 3;             // 0..3

    const int c  = blockIdx.x;
    const int n  = c % NB;
    const int bh = c / NB;
    const int h  = bh % HH;
    const long base = ((long)bh * SS + (long)n * BLK) * DD;

    const float* qb = q + base;
    const float* kb = k + base;
    const float* vb = v + base;
    float*       ob = out + base;

    // loader mapping: fixed column group c4, rows (tid>>5)+8*j
    const int lrow = tid >> 5;             // 0..7
    const int c4   = (tid & 31) * 4;
    const float4 sc4 = *(const float4*)(sc + h * DD + c4);
    const float4 bi4 = *(const float4*)(bi + h * DD + c4);

    // ========== Phase 1: S_dm = phi(K)^T V  (128x128, K-dim 512), Z = sum phi(K)
    // warp tiling: wd in {0,1} covers 64 d-rows; wm in {0..3} covers 32 m-cols
    const int wd = w & 1;
    const int wm = w >> 1;

    float acc[4][4][4];
    #pragma unroll
    for (int a = 0; a < 4; ++a)
        #pragma unroll
        for (int b = 0; b < 4; ++b)
            #pragma unroll
            for (int r = 0; r < 4; ++r) acc[a][b][r] = 0.0f;

    float4 zacc = make_float4(0.f, 0.f, 0.f, 0.f);

    // prefetch chunk 0 (16 s-rows)
    float4 kv[2], vv[2];
    #pragma unroll
    for (int j = 0; j < 2; ++j) {
        const int r = lrow + 8 * j;
        kv[j] = *(const float4*)(kb + (long)r * DD + c4);
        vv[j] = *(const float4*)(vb + (long)r * DD + c4);
    }

    for (int ch = 0; ch < BLK / 16; ++ch) {
        // stage current chunk (phi(K) as tf32, V as tf32)
        #pragma unroll
        for (int j = 0; j < 2; ++j) {
            const int r = lrow + 8 * j;
            float4 p;
            p.x = phi_elu1(fmaf(kv[j].x, sc4.x, bi4.x));
            p.y = phi_elu1(fmaf(kv[j].y, sc4.y, bi4.y));
            p.z = phi_elu1(fmaf(kv[j].z, sc4.z, bi4.z));
            p.w = phi_elu1(fmaf(kv[j].w, sc4.w, bi4.w));
            zacc.x += p.x; zacc.y += p.y; zacc.z += p.z; zacc.w += p.w;
            uint4 pu = make_uint4(f2tf(p.x), f2tf(p.y), f2tf(p.z), f2tf(p.w));
            *(uint4*)(phik_s + r * SPAD + c4) = pu;
            uint4 vu = make_uint4(f2tf(vv[j].x), f2tf(vv[j].y), f2tf(vv[j].z), f2tf(vv[j].w));
            *(uint4*)(v_s + r * VPAD + c4) = vu;
        }
        __syncthreads();

        // prefetch next chunk (overlaps mma)
        if (ch < BLK / 16 - 1) {
            const float* kc = kb + (long)(ch + 1) * 16 * DD;
            const float* vc = vb + (long)(ch + 1) * 16 * DD;
            #pragma unroll
            for (int j = 0; j < 2; ++j) {
                const int r = lrow + 8 * j;
                kv[j] = *(const float4*)(kc + (long)r * DD + c4);
                vv[j] = *(const float4*)(vc + (long)r * DD + c4);
            }
        }

        // mma: 2 k-steps of 8 over the 16 staged s-rows
        #pragma unroll
        for (int ks = 0; ks < 2; ++ks) {
            const int sb = ks * 8;
            // B fragments (V), cached for all d-tiles
            uint32_t B[4][2];
            #pragma unroll
            for (int mt = 0; mt < 4; ++mt) {
                const int m = wm * 32 + mt * 8 + g;
                B[mt][0] = __float_as_uint(v_s[(sb + t) * VPAD + m]);
                B[mt][1] = __float_as_uint(v_s[(sb + t + 4) * VPAD + m]);
            }
            #pragma unroll
            for (int dt = 0; dt < 4; ++dt) {
                const int d0 = wd * 64 + dt * 16;
                uint32_t A[4];
                A[0] = __float_as_uint(phik_s[(sb + t)     * SPAD + d0 + g]);
                A[1] = __float_as_uint(phik_s[(sb + t)     * SPAD + d0 + g + 8]);
                A[2] = __float_as_uint(phik_s[(sb + t + 4) * SPAD + d0 + g]);
                A[3] = __float_as_uint(phik_s[(sb + t + 4) * SPAD + d0 + g + 8]);
                #pragma unroll
                for (int mt = 0; mt < 4; ++mt)
                    mma_tf32(acc[dt][mt], A, B[mt]);
            }
        }
        __syncthreads();
    }

    // write S_dm to smem
    #pragma unroll
    for (int dt = 0; dt < 4; ++dt) {
        const int d0 = wd * 64 + dt * 16;
        #pragma unroll
        for (int mt = 0; mt < 4; ++mt) {
            const int m = wm * 32 + mt * 8 + 2 * t;
            *(float2*)(Sdm + (d0 + g)     * VPAD + m) = make_float2(acc[dt][mt][0], acc[dt][mt][1]);
            *(float2*)(Sdm + (d0 + g + 8) * VPAD + m) = make_float2(acc[dt][mt][2], acc[dt][mt][3]);
        }
    }

    // reduce Z (zacc partials: 8 per column) -- reuse stage area
    *(float4*)(stage + lrow * DD + c4) = zacc;
    __syncthreads();
    if (tid < DD) {
        float s = 0.0f;
        #pragma unroll
        for (int r = 0; r < 8; ++r) s += stage[r * DD + tid];
        Zsm[tid] = s;
    }
    __syncthreads();

    // ========== Phase 2: out = phi(Q) S_dm / (phi(Q).Z + eps)
    // chunk = 64 s-rows; warp tiling: s0 = (w&3)*16, m0 = (w>>2)*64 (8 n-tiles)
    const int s0 = (w & 3) * 16;
    const int m0 = (w >> 2) * 64;

    // prefetch Q chunk 0
    float4 qreg[8];
    #pragma unroll
    for (int j = 0; j < 8; ++j) {
        const int r = lrow + 8 * j;
        qreg[j] = *(const float4*)(qb + (long)r * DD + c4);
    }

    for (int chq = 0; chq < BLK / 64; ++chq) {
        // stage phi(Q) as tf32
        #pragma unroll
        for (int j = 0; j < 8; ++j) {
            const int r = lrow + 8 * j;
            float4 p;
            p.x = phi_elu1(fmaf(qreg[j].x, sc4.x, bi4.x));
            p.y = phi_elu1(fmaf(qreg[j].y, sc4.y, bi4.y));
            p.z = phi_elu1(fmaf(qreg[j].z, sc4.z, bi4.z));
            p.w = phi_elu1(fmaf(qreg[j].w, sc4.w, bi4.w));
            uint4 pu = make_uint4(f2tf(p.x), f2tf(p.y), f2tf(p.z), f2tf(p.w));
            *(uint4*)(stage + r * SPAD + c4) = pu;
        }
        __syncthreads();

        // prefetch next Q chunk (overlaps den + mma)
        if (chq < BLK / 64 - 1) {
            const float* qc = qb + (long)(chq + 1) * 64 * DD;
            #pragma unroll
            for (int j = 0; j < 8; ++j) {
                const int r = lrow + 8 * j;
                qreg[j] = *(const float4*)(qc + (long)r * DD + c4);
            }
        }

        // den[row] = phiQ(row) . Z + eps  (4 lanes per row, quarter dots + shuffle)
        {
            const int row  = tid >> 2;
            const int part = tid & 3;
            float s = 0.0f;
            #pragma unroll
            for (int d4 = part * 32; d4 < part * 32 + 32; d4 += 4) {
                const float4 a = *(const float4*)(stage + row * SPAD + d4);
                const float4 z = *(const float4*)(Zsm + d4);
                s = fmaf(a.x, z.x, s);
                s = fmaf(a.y, z.y, s);
                s = fmaf(a.z, z.z, s);
                s = fmaf(a.w, z.w, s);
            }
            s += __shfl_xor_sync(0xffffffffu, s, 1);
            s += __shfl_xor_sync(0xffffffffu, s, 2);
            if (part == 0) den[row] = s + EPS_F;
        }

        // GEMM: 64(s) x 128(m), K = 128(d). warp: 16s x 64m -> 8 n-tiles
        float accq[8][4];
        #pragma unroll
        for (int mt = 0; mt < 8; ++mt)
            #pragma unroll
            for (int r = 0; r < 4; ++r) accq[mt][r] = 0.0f;

        #pragma unroll
        for (int kk = 0; kk < DD / 8; ++kk) {
            const int kb8 = kk * 8;
            uint32_t A[4];
            A[0] = __float_as_uint(stage[(s0 + g)     * SPAD + kb8 + t]);
            A[1] = __float_as_uint(stage[(s0 + g + 8) * SPAD + kb8 + t]);
            A[2] = __float_as_uint(stage[(s0 + g)     * SPAD + kb8 + t + 4]);
            A[3] = __float_as_uint(stage[(s0 + g + 8) * SPAD + kb8 + t + 4]);
            #pragma unroll
            for (int mt = 0; mt < 8; ++mt) {
                const int m = m0 + mt * 8 + g;
                uint32_t B[2];
                B[0] = __float_as_uint(Sdm[(kb8 + t)     * VPAD + m]);
                B[1] = __float_as_uint(Sdm[(kb8 + t + 4) * VPAD + m]);
                mma_tf32(accq[mt], A, B);
            }
        }
        __syncthreads();   // den visible; stage reads complete

        // epilogue: scale by 1/den, store
        const int r0 = chq * 64 + s0 + g;
        const float inv0 = 1.0f / den[s0 + g];
        const float inv1 = 1.0f / den[s0 + g + 8];
        #pragma unroll
        for (int mt = 0; mt < 8; ++mt) {
            const int m = m0 + mt * 8 + 2 * t;
            *(float2*)(ob + (long)r0 * DD + m) =
                make_float2(accq[mt][0] * inv0, accq[mt][1] * inv0);
            *(float2*)(ob + (long)(r0 + 8) * DD + m) =
                make_float2(accq[mt][2] * inv1, accq[mt][3] * inv1);
        }
    }
}

extern "C" void kernel_launch(void* const* d_in, const int* in_sizes, int n_in,
                              void* d_out, int out_size) {
    const float* q  = (const float*)d_in[0];
    const float* k  = (const float*)d_in[1];
    const float* v  = (const float*)d_in[2];
    const float* sc = (const float*)d_in[3];
    const float* bi = (const float*)d_in[4];
    float* out = (float*)d_out;

    cudaFuncSetAttribute(lin_attn_tc,
                         cudaFuncAttributeMaxDynamicSharedMemorySize, SMEM_BYTES);
    lin_attn_tc<<<NCTA, NT, SMEM_BYTES>>>(q, k, v, sc, bi, out);
}

// round 5
// speedup vs baseline: 1.0046x; 1.0046x over previous
#include <cuda_runtime.h>
#include <cstdint>

// Problem shape (fixed by the dataset instance)
#define BB   2
#define HH   32
#define SS   4096
#define DD   128
#define BLK  512
#define NB   (SS / BLK)          // 8
#define NCTA (BB * HH * NB)      // 512
#define NT   256
#define EPS_F 1e-6f

// Smem strides chosen for conflict-free mma fragment loads:
//  A-fragment loads (stride SPAD=132): bank = (4t + g) -> 32 distinct
//  B-fragment loads (stride VPAD=136): bank = (8t + g) -> 32 distinct
#define SPAD 132
#define VPAD 136

// Shared memory layout (floats)
#define SDM_OFF   0                        // S_dm: 128 x 136        (17408)
#define STAGE_OFF (DD * VPAD)              // stage: 64 x 132 region  (8448)
#define Z_OFF     (STAGE_OFF + 64 * SPAD)  // Z[128]
#define DEN_OFF   (Z_OFF + DD)             // den[64]
#define SMEM_FLOATS (DEN_OFF + 64)
#define SMEM_BYTES  (SMEM_FLOATS * 4)      // 104192 B -> 2 CTAs/SM

__device__ __forceinline__ float phi_elu1(float y) {
    return y > 0.0f ? y + 1.0f : __expf(y);
}

__device__ __forceinline__ uint32_t f2tf(float x) {
    uint32_t u;
    asm("cvt.rna.tf32.f32 %0, %1;" : "=r"(u) : "f"(x));
    return u;
}

__device__ __forceinline__ void mma_tf32(float* c, const uint32_t* a, const uint32_t* b) {
    asm volatile(
        "mma.sync.aligned.m16n8k8.row.col.f32.tf32.tf32.f32 "
        "{%0,%1,%2,%3}, {%4,%5,%6,%7}, {%8,%9}, {%0,%1,%2,%3};\n"
        : "+f"(c[0]), "+f"(c[1]), "+f"(c[2]), "+f"(c[3])
        : "r"(a[0]), "r"(a[1]), "r"(a[2]), "r"(a[3]), "r"(b[0]), "r"(b[1]));
}

extern "C" __global__ void __launch_bounds__(NT, 2)
lin_attn_tc(const float* __restrict__ q,
            const float* __restrict__ k,
            const float* __restrict__ v,
            const float* __restrict__ sc,
            const float* __restrict__ bi,
            float* __restrict__ out)
{
    extern __shared__ float sm[];
    float* Sdm   = sm + SDM_OFF;           // [128][VPAD]
    float* stage = sm + STAGE_OFF;         // phase1: phiK[16][SPAD] + V[16][VPAD]; phase2: phiQ[64][SPAD]
    float* Zsm   = sm + Z_OFF;             // [128]
    float* den   = sm + DEN_OFF;           // [64]

    float* phik_s = stage;                 // 16 x SPAD
    float* v_s    = stage + 16 * SPAD;     // 16 x VPAD

    const int tid  = threadIdx.x;
    const int lane = tid & 31;
    const int w    = tid >> 5;             // warp 0..7
    const int g    = lane >> 2;            // 0..7
    const int t    = lane & 3;             // 0..3

    const int c  = blockIdx.x;
    const int n  = c % NB;
    const int bh = c / NB;
    const int h  = bh % HH;
    const long base = ((long)bh * SS + (long)n * BLK) * DD;

    const float* qb = q + base;
    const float* kb = k + base;
    const float* vb = v + base;
    float*       ob = out + base;

    // loader mapping: fixed column group c4, rows (tid>>5)+8*j
    const int lrow = tid >> 5;             // 0..7
    const int c4   = (tid & 31) * 4;
    const float4 sc4 = *(const float4*)(sc + h * DD + c4);
    const float4 bi4 = *(const float4*)(bi + h * DD + c4);

    // ========== Phase 1: S_dm = phi(K)^T V  (128x128, K-dim 512), Z = sum phi(K)
    // warp tiling: wd in {0,1} covers 64 d-rows; wm in {0..3} covers 32 m-cols
    const int wd = w & 1;
    const int wm = w >> 1;

    float acc[4][4][4];
    #pragma unroll
    for (int a = 0; a < 4; ++a)
        #pragma unroll
        for (int b = 0; b < 4; ++b)
            #pragma unroll
            for (int r = 0; r < 4; ++r) acc[a][b][r] = 0.0f;

    float4 zacc = make_float4(0.f, 0.f, 0.f, 0.f);

    // prefetch chunk 0 (16 s-rows)
    float4 kv[2], vv[2];
    #pragma unroll
    for (int j = 0; j < 2; ++j) {
        const int r = lrow + 8 * j;
        kv[j] = *(const float4*)(kb + (long)r * DD + c4);
        vv[j] = *(const float4*)(vb + (long)r * DD + c4);
    }

    for (int ch = 0; ch < BLK / 16; ++ch) {
        // stage current chunk (phi(K) as tf32, V as tf32)
        #pragma unroll
        for (int j = 0; j < 2; ++j) {
            const int r = lrow + 8 * j;
            float4 p;
            p.x = phi_elu1(fmaf(kv[j].x, sc4.x, bi4.x));
            p.y = phi_elu1(fmaf(kv[j].y, sc4.y, bi4.y));
            p.z = phi_elu1(fmaf(kv[j].z, sc4.z, bi4.z));
            p.w = phi_elu1(fmaf(kv[j].w, sc4.w, bi4.w));
            zacc.x += p.x; zacc.y += p.y; zacc.z += p.z; zacc.w += p.w;
            uint4 pu = make_uint4(f2tf(p.x), f2tf(p.y), f2tf(p.z), f2tf(p.w));
            *(uint4*)(phik_s + r * SPAD + c4) = pu;
            uint4 vu = make_uint4(f2tf(vv[j].x), f2tf(vv[j].y), f2tf(vv[j].z), f2tf(vv[j].w));
            *(uint4*)(v_s + r * VPAD + c4) = vu;
        }
        __syncthreads();

        // prefetch next chunk (overlaps mma)
        if (ch < BLK / 16 - 1) {
            const float* kc = kb + (long)(ch + 1) * 16 * DD;
            const float* vc = vb + (long)(ch + 1) * 16 * DD;
            #pragma unroll
            for (int j = 0; j < 2; ++j) {
                const int r = lrow + 8 * j;
                kv[j] = *(const float4*)(kc + (long)r * DD + c4);
                vv[j] = *(const float4*)(vc + (long)r * DD + c4);
            }
        }

        // mma: 2 k-steps of 8 over the 16 staged s-rows
        #pragma unroll
        for (int ks = 0; ks < 2; ++ks) {
            const int sb = ks * 8;
            // B fragments (V), cached for all d-tiles
            uint32_t B[4][2];
            #pragma unroll
            for (int mt = 0; mt < 4; ++mt) {
                const int m = wm * 32 + mt * 8 + g;
                B[mt][0] = __float_as_uint(v_s[(sb + t) * VPAD + m]);
                B[mt][1] = __float_as_uint(v_s[(sb + t + 4) * VPAD + m]);
            }
            #pragma unroll
            for (int dt = 0; dt < 4; ++dt) {
                const int d0 = wd * 64 + dt * 16;
                uint32_t A[4];
                A[0] = __float_as_uint(phik_s[(sb + t)     * SPAD + d0 + g]);
                A[1] = __float_as_uint(phik_s[(sb + t)     * SPAD + d0 + g + 8]);
                A[2] = __float_as_uint(phik_s[(sb + t + 4) * SPAD + d0 + g]);
                A[3] = __float_as_uint(phik_s[(sb + t + 4) * SPAD + d0 + g + 8]);
                #pragma unroll
                for (int mt = 0; mt < 4; ++mt)
                    mma_tf32(acc[dt][mt], A, B[mt]);
            }
        }
        __syncthreads();
    }

    // write S_dm to smem
    #pragma unroll
    for (int dt = 0; dt < 4; ++dt) {
        const int d0 = wd * 64 + dt * 16;
        #pragma unroll
        for (int mt = 0; mt < 4; ++mt) {
            const int m = wm * 32 + mt * 8 + 2 * t;
            *(float2*)(Sdm + (d0 + g)     * VPAD + m) = make_float2(acc[dt][mt][0], acc[dt][mt][1]);
            *(float2*)(Sdm + (d0 + g + 8) * VPAD + m) = make_float2(acc[dt][mt][2], acc[dt][mt][3]);
        }
    }

    // reduce Z (zacc partials: 8 per column) -- reuse stage area
    *(float4*)(stage + lrow * DD + c4) = zacc;
    __syncthreads();
    if (tid < DD) {
        float s = 0.0f;
        #pragma unroll
        for (int r = 0; r < 8; ++r) s += stage[r * DD + tid];
        Zsm[tid] = s;
    }
    __syncthreads();

    // ========== Phase 2: out = phi(Q) S_dm / (phi(Q).Z + eps)
    // chunk = 64 s-rows; warp tiling: s0 = (w&3)*16, m0 = (w>>2)*64 (8 n-tiles)
    const int s0 = (w & 3) * 16;
    const int m0 = (w >> 2) * 64;

    // prefetch Q chunk 0
    float4 qreg[8];
    #pragma unroll
    for (int j = 0; j < 8; ++j) {
        const int r = lrow + 8 * j;
        qreg[j] = *(const float4*)(qb + (long)r * DD + c4);
    }

    for (int chq = 0; chq < BLK / 64; ++chq) {
        // stage phi(Q) as tf32
        #pragma unroll
        for (int j = 0; j < 8; ++j) {
            const int r = lrow + 8 * j;
            float4 p;
            p.x = phi_elu1(fmaf(qreg[j].x, sc4.x, bi4.x));
            p.y = phi_elu1(fmaf(qreg[j].y, sc4.y, bi4.y));
            p.z = phi_elu1(fmaf(qreg[j].z, sc4.z, bi4.z));
            p.w = phi_elu1(fmaf(qreg[j].w, sc4.w, bi4.w));
            uint4 pu = make_uint4(f2tf(p.x), f2tf(p.y), f2tf(p.z), f2tf(p.w));
            *(uint4*)(stage + r * SPAD + c4) = pu;
        }
        __syncthreads();

        // prefetch next Q chunk (overlaps den + mma)
        if (chq < BLK / 64 - 1) {
            const float* qc = qb + (long)(chq + 1) * 64 * DD;
            #pragma unroll
            for (int j = 0; j < 8; ++j) {
                const int r = lrow + 8 * j;
                qreg[j] = *(const float4*)(qc + (long)r * DD + c4);
            }
        }

        // den[row] = phiQ(row) . Z + eps  (4 lanes per row, quarter dots + shuffle)
        {
            const int row  = tid >> 2;
            const int part = tid & 3;
            float s = 0.0f;
            #pragma unroll
            for (int d4 = part * 32; d4 < part * 32 + 32; d4 += 4) {
                const float4 a = *(const float4*)(stage + row * SPAD + d4);
                const float4 z = *(const float4*)(Zsm + d4);
                s = fmaf(a.x, z.x, s);
                s = fmaf(a.y, z.y, s);
                s = fmaf(a.z, z.z, s);
                s = fmaf(a.w, z.w, s);
            }
            s += __shfl_xor_sync(0xffffffffu, s, 1);
            s += __shfl_xor_sync(0xffffffffu, s, 2);
            if (part == 0) den[row] = s + EPS_F;
        }

        // GEMM: 64(s) x 128(m), K = 128(d). warp: 16s x 64m -> 8 n-tiles
        float accq[8][4];
        #pragma unroll
        for (int mt = 0; mt < 8; ++mt)
            #pragma unroll
            for (int r = 0; r < 4; ++r) accq[mt][r] = 0.0f;

        #pragma unroll
        for (int kk = 0; kk < DD / 8; ++kk) {
            const int kb8 = kk * 8;
            uint32_t A[4];
            A[0] = __float_as_uint(stage[(s0 + g)     * SPAD + kb8 + t]);
            A[1] = __float_as_uint(stage[(s0 + g + 8) * SPAD + kb8 + t]);
            A[2] = __float_as_uint(stage[(s0 + g)     * SPAD + kb8 + t + 4]);
            A[3] = __float_as_uint(stage[(s0 + g + 8) * SPAD + kb8 + t + 4]);
            #pragma unroll
            for (int mt = 0; mt < 8; ++mt) {
                const int m = m0 + mt * 8 + g;
                uint32_t B[2];
                B[0] = __float_as_uint(Sdm[(kb8 + t)     * VPAD + m]);
                B[1] = __float_as_uint(Sdm[(kb8 + t + 4) * VPAD + m]);
                mma_tf32(accq[mt], A, B);
            }
        }
        __syncthreads();   // den visible; stage reads complete

        // epilogue: scale by 1/den, store
        const int r0 = chq * 64 + s0 + g;
        const float inv0 = 1.0f / den[s0 + g];
        const float inv1 = 1.0f / den[s0 + g + 8];
        #pragma unroll
        for (int mt = 0; mt < 8; ++mt) {
            const int m = m0 + mt * 8 + 2 * t;
            *(float2*)(ob + (long)r0 * DD + m) =
                make_float2(accq[mt][0] * inv0, accq[mt][1] * inv0);
            *(float2*)(ob + (long)(r0 + 8) * DD + m) =
                make_float2(accq[mt][2] * inv1, accq[mt][3] * inv1);
        }
    }
}

extern "C" void kernel_launch(void* const* d_in, const int* in_sizes, int n_in,
                              void* d_out, int out_size) {
    const float* q  = (const float*)d_in[0];
    const float* k  = (const float*)d_in[1];
    const float* v  = (const float*)d_in[2];
    const float* sc = (const float*)d_in[3];
    const float* bi = (const float*)d_in[4];
    float* out = (float*)d_out;

    cudaFuncSetAttribute(lin_attn_tc,
                         cudaFuncAttributeMaxDynamicSharedMemorySize, SMEM_BYTES);
    lin_attn_tc<<<NCTA, NT, SMEM_BYTES>>>(q, k, v, sc, bi, out);
}

// round 6
// speedup vs baseline: 1.1764x; 1.1709x over previous
#include <cuda_runtime.h>
#include <cstdint>

// Problem shape (fixed by the dataset instance)
#define BB   2
#define HH   32
#define SS   4096
#define DD   128
#define BLK  512
#define NB   (SS / BLK)          // 8
#define NCTA (BB * HH * NB)      // 512
#define NT   256
#define EPS_F 1e-6f

// Smem strides chosen for conflict-free mma fragment loads:
//  A-fragment loads (stride SPAD=132): bank = (4g + t) -> 32 distinct
//  B-fragment loads (stride VPAD=136): bank = (8t + g) -> 32 distinct
#define SPAD 132
#define VPAD 136

// Shared layout (floats):
//  Sdm  : 128 x VPAD, cols 0..127 = S_dm, col 128 = Z (fused den operand)
//  stage: phase1 = 2 double-buffered (16xSPAD phiK + 16xVPAD V); phase2 = 64xSPAD phiQ
//  den  : 64
#define BUF_FLOATS  (16 * SPAD + 16 * VPAD)       // 4288
#define STAGE_OFF   (DD * VPAD)                   // 17408
#define DEN_OFF     (STAGE_OFF + 2 * BUF_FLOATS)  // 25984
#define SMEM_FLOATS (DEN_OFF + 64)                // 26048
#define SMEM_BYTES  (SMEM_FLOATS * 4)             // 104192 -> 2 CTAs/SM

__device__ __forceinline__ float phi_elu1(float y) {
    return y > 0.0f ? y + 1.0f : __expf(y);
}

__device__ __forceinline__ uint32_t f2tf(float x) {
    uint32_t u;
    asm("cvt.rna.tf32.f32 %0, %1;" : "=r"(u) : "f"(x));
    return u;
}

__device__ __forceinline__ void mma_tf32(float* c, const uint32_t* a, const uint32_t* b) {
    asm volatile(
        "mma.sync.aligned.m16n8k8.row.col.f32.tf32.tf32.f32 "
        "{%0,%1,%2,%3}, {%4,%5,%6,%7}, {%8,%9}, {%0,%1,%2,%3};\n"
        : "+f"(c[0]), "+f"(c[1]), "+f"(c[2]), "+f"(c[3])
        : "r"(a[0]), "r"(a[1]), "r"(a[2]), "r"(a[3]), "r"(b[0]), "r"(b[1]));
}

extern "C" __global__ void __launch_bounds__(NT, 2)
lin_attn_tc2(const float* __restrict__ q,
             const float* __restrict__ k,
             const float* __restrict__ v,
             const float* __restrict__ sc,
             const float* __restrict__ bi,
             float* __restrict__ out)
{
    extern __shared__ float sm[];
    float* Sdm   = sm;                 // [128][VPAD]
    float* stage = sm + STAGE_OFF;
    float* den   = sm + DEN_OFF;

    const int tid  = threadIdx.x;
    const int lane = tid & 31;
    const int w    = tid >> 5;          // warp 0..7
    const int g    = lane >> 2;         // 0..7
    const int t    = lane & 3;          // 0..3

    const int c  = blockIdx.x;
    const int n  = c % NB;
    const int bh = c / NB;
    const int h  = bh % HH;
    const long base = ((long)bh * SS + (long)n * BLK) * DD;

    const float* qb = q + base;
    const float* kb = k + base;
    const float* vb = v + base;
    float*       ob = out + base;

    const int lrow = w;                 // loader row 0..7
    const int c4   = lane * 4;          // loader column group
    const float4 sc4 = *(const float4*)(sc + h * DD + c4);
    const float4 bi4 = *(const float4*)(bi + h * DD + c4);

    // ================= Phase 1: S_dm = phi(K)^T V ; Z = sum phi(K) ==========
    // warp tiling: wd in {0,1} -> 64 d-rows; wm1 in {0..3} -> 32 m-cols
    const int wd  = w & 1;
    const int wm1 = w >> 1;

    float acc[4][4][4];
    #pragma unroll
    for (int a = 0; a < 4; ++a)
        #pragma unroll
        for (int b = 0; b < 4; ++b)
            #pragma unroll
            for (int r = 0; r < 4; ++r) acc[a][b][r] = 0.0f;

    float4 zacc = make_float4(0.f, 0.f, 0.f, 0.f);
    float4 kv[2], vv[2];

#define LOADCH(ch) do {                                                     \
        const float* kc_ = kb + (long)(ch) * 16 * DD;                       \
        const float* vc_ = vb + (long)(ch) * 16 * DD;                       \
        kv[0] = *(const float4*)(kc_ + (long)lrow * DD + c4);               \
        kv[1] = *(const float4*)(kc_ + (long)(lrow + 8) * DD + c4);         \
        vv[0] = *(const float4*)(vc_ + (long)lrow * DD + c4);               \
        vv[1] = *(const float4*)(vc_ + (long)(lrow + 8) * DD + c4);         \
    } while (0)

#define STORECH(pk_, pv_) do {                                              \
        _Pragma("unroll")                                                   \
        for (int j_ = 0; j_ < 2; ++j_) {                                    \
            const int r_ = lrow + 8 * j_;                                   \
            float4 p_;                                                      \
            p_.x = phi_elu1(fmaf(kv[j_].x, sc4.x, bi4.x));                  \
            p_.y = phi_elu1(fmaf(kv[j_].y, sc4.y, bi4.y));                  \
            p_.z = phi_elu1(fmaf(kv[j_].z, sc4.z, bi4.z));                  \
            p_.w = phi_elu1(fmaf(kv[j_].w, sc4.w, bi4.w));                  \
            zacc.x += p_.x; zacc.y += p_.y; zacc.z += p_.z; zacc.w += p_.w; \
            uint4 pu_ = make_uint4(f2tf(p_.x), f2tf(p_.y),                  \
                                   f2tf(p_.z), f2tf(p_.w));                 \
            *(uint4*)((pk_) + r_ * SPAD + c4) = pu_;                        \
            uint4 vu_ = make_uint4(f2tf(vv[j_].x), f2tf(vv[j_].y),          \
                                   f2tf(vv[j_].z), f2tf(vv[j_].w));         \
            *(uint4*)((pv_) + r_ * VPAD + c4) = vu_;                        \
        }                                                                   \
    } while (0)

    // prologue: chunk 0 -> buf0, prefetch chunk 1
    LOADCH(0);
    STORECH(stage, stage + 16 * SPAD);
    LOADCH(1);
    __syncthreads();

    for (int ch = 0; ch < BLK / 16; ++ch) {
        const int p = ch & 1;
        float* pk = stage + p * BUF_FLOATS;
        float* pv = pk + 16 * SPAD;

        // pipeline: store chunk ch+1 into alternate buffer, prefetch ch+2
        if (ch < BLK / 16 - 1) {
            float* npk = stage + (p ^ 1) * BUF_FLOATS;
            STORECH(npk, npk + 16 * SPAD);
        }
        if (ch < BLK / 16 - 2) LOADCH(ch + 2);

        // mma on buffer p: 2 k-steps of 8 over 16 staged s-rows
        #pragma unroll
        for (int ks = 0; ks < 2; ++ks) {
            const int sb = ks * 8;
            uint32_t B[4][2];
            #pragma unroll
            for (int mt = 0; mt < 4; ++mt) {
                const int m = wm1 * 32 + mt * 8 + g;
                B[mt][0] = __float_as_uint(pv[(sb + t) * VPAD + m]);
                B[mt][1] = __float_as_uint(pv[(sb + t + 4) * VPAD + m]);
            }
            #pragma unroll
            for (int dt = 0; dt < 4; ++dt) {
                const int d0 = wd * 64 + dt * 16;
                uint32_t A[4];
                A[0] = __float_as_uint(pk[(sb + t)     * SPAD + d0 + g]);
                A[1] = __float_as_uint(pk[(sb + t)     * SPAD + d0 + g + 8]);
                A[2] = __float_as_uint(pk[(sb + t + 4) * SPAD + d0 + g]);
                A[3] = __float_as_uint(pk[(sb + t + 4) * SPAD + d0 + g + 8]);
                #pragma unroll
                for (int mt = 0; mt < 4; ++mt)
                    mma_tf32(acc[dt][mt], A, B[mt]);
            }
        }
        __syncthreads();
    }

    // write S_dm to smem
    #pragma unroll
    for (int dt = 0; dt < 4; ++dt) {
        const int d0 = wd * 64 + dt * 16;
        #pragma unroll
        for (int mt = 0; mt < 4; ++mt) {
            const int m = wm1 * 32 + mt * 8 + 2 * t;
            *(float2*)(Sdm + (d0 + g)     * VPAD + m) = make_float2(acc[dt][mt][0], acc[dt][mt][1]);
            *(float2*)(Sdm + (d0 + g + 8) * VPAD + m) = make_float2(acc[dt][mt][2], acc[dt][mt][3]);
        }
    }

    // prefetch Q chunk 0 (overlaps Z reduction)
    float4 qreg[8];
    #pragma unroll
    for (int j = 0; j < 8; ++j)
        qreg[j] = *(const float4*)(qb + (long)(lrow + 8 * j) * DD + c4);

    // reduce Z into Sdm column 128 (cols 129..135 zeroed)
    *(float4*)(stage + lrow * DD + c4) = zacc;
    __syncthreads();
    if (tid < DD) {
        float s = 0.0f;
        #pragma unroll
        for (int r = 0; r < 8; ++r) s += stage[r * DD + tid];
        *(float4*)(Sdm + tid * VPAD + 128) = make_float4(s, 0.f, 0.f, 0.f);
        *(float4*)(Sdm + tid * VPAD + 132) = make_float4(0.f, 0.f, 0.f, 0.f);
    }
    __syncthreads();

    // ===== Phase 2: out = phi(Q) [S_dm | Z] ; den fused as column 128 ======
    // chunk = 64 s-rows; warp grid 2s x 4m: tile 32s x 32m
    const int ws = w & 1;
    const int wm = w >> 1;
    const int s0 = ws * 32;
    const int m0 = wm * 32;

    for (int chq = 0; chq < BLK / 64; ++chq) {
        // stage phi(Q) as tf32 (64 rows x SPAD)
        #pragma unroll
        for (int j = 0; j < 8; ++j) {
            const int r = lrow + 8 * j;
            float4 p;
            p.x = phi_elu1(fmaf(qreg[j].x, sc4.x, bi4.x));
            p.y = phi_elu1(fmaf(qreg[j].y, sc4.y, bi4.y));
            p.z = phi_elu1(fmaf(qreg[j].z, sc4.z, bi4.z));
            p.w = phi_elu1(fmaf(qreg[j].w, sc4.w, bi4.w));
            uint4 pu = make_uint4(f2tf(p.x), f2tf(p.y), f2tf(p.z), f2tf(p.w));
            *(uint4*)(stage + r * SPAD + c4) = pu;
        }
        __syncthreads();

        // prefetch next Q chunk (overlaps mma)
        if (chq < BLK / 64 - 1) {
            const float* qc = qb + (long)(chq + 1) * 64 * DD;
            #pragma unroll
            for (int j = 0; j < 8; ++j)
                qreg[j] = *(const float4*)(qc + (long)(lrow + 8 * j) * DD + c4);
        }

        // GEMM: warp computes 32(s) x 32(m) (+ Z column for wm==0), K = 128
        float accq[2][5][4];
        #pragma unroll
        for (int st = 0; st < 2; ++st)
            #pragma unroll
            for (int mt = 0; mt < 5; ++mt)
                #pragma unroll
                for (int r = 0; r < 4; ++r) accq[st][mt][r] = 0.0f;

        #pragma unroll
        for (int kk = 0; kk < DD / 8; ++kk) {
            const int kb8 = kk * 8;
            uint32_t A[2][4];
            #pragma unroll
            for (int st = 0; st < 2; ++st) {
                const int row = s0 + st * 16;
                A[st][0] = __float_as_uint(stage[(row + g)     * SPAD + kb8 + t]);
                A[st][1] = __float_as_uint(stage[(row + g + 8) * SPAD + kb8 + t]);
                A[st][2] = __float_as_uint(stage[(row + g)     * SPAD + kb8 + t + 4]);
                A[st][3] = __float_as_uint(stage[(row + g + 8) * SPAD + kb8 + t + 4]);
            }
            #pragma unroll
            for (int mt = 0; mt < 4; ++mt) {
                const int m = m0 + mt * 8 + g;
                uint32_t B[2];
                B[0] = __float_as_uint(Sdm[(kb8 + t)     * VPAD + m]);
                B[1] = __float_as_uint(Sdm[(kb8 + t + 4) * VPAD + m]);
                mma_tf32(accq[0][mt], A[0], B);
                mma_tf32(accq[1][mt], A[1], B);
            }
            if (wm == 0) {
                const int m = 128 + g;      // Z column tile
                uint32_t B[2];
                B[0] = __float_as_uint(Sdm[(kb8 + t)     * VPAD + m]);
                B[1] = __float_as_uint(Sdm[(kb8 + t + 4) * VPAD + m]);
                mma_tf32(accq[0][4], A[0], B);
                mma_tf32(accq[1][4], A[1], B);
            }
        }

        // den = Z-column result (col 128 -> n=0 of tile 4 -> lanes t==0, c0/c2)
        if (wm == 0 && t == 0) {
            #pragma unroll
            for (int st = 0; st < 2; ++st) {
                den[s0 + st * 16 + g]     = accq[st][4][0] + EPS_F;
                den[s0 + st * 16 + g + 8] = accq[st][4][2] + EPS_F;
            }
        }
        __syncthreads();   // den visible; stage reads complete

        // epilogue: scale by 1/den, store
        #pragma unroll
        for (int st = 0; st < 2; ++st) {
            const int rr   = s0 + st * 16 + g;
            const int r0   = chq * 64 + rr;
            const float i0 = 1.0f / den[rr];
            const float i1 = 1.0f / den[rr + 8];
            #pragma unroll
            for (int mt = 0; mt < 4; ++mt) {
                const int m = m0 + mt * 8 + 2 * t;
                *(float2*)(ob + (long)r0 * DD + m) =
                    make_float2(accq[st][mt][0] * i0, accq[st][mt][1] * i0);
                *(float2*)(ob + (long)(r0 + 8) * DD + m) =
                    make_float2(accq[st][mt][2] * i1, accq[st][mt][3] * i1);
            }
        }
    }
}

extern "C" void kernel_launch(void* const* d_in, const int* in_sizes, int n_in,
                              void* d_out, int out_size) {
    const float* q  = (const float*)d_in[0];
    const float* k  = (const float*)d_in[1];
    const float* v  = (const float*)d_in[2];
    const float* sc = (const float*)d_in[3];
    const float* bi = (const float*)d_in[4];
    float* out = (float*)d_out;

    cudaFuncSetAttribute(lin_attn_tc2,
                         cudaFuncAttributeMaxDynamicSharedMemorySize, SMEM_BYTES);
    lin_attn_tc2<<<NCTA, NT, SMEM_BYTES>>>(q, k, v, sc, bi, out);
}

// round 7
// speedup vs baseline: 1.1841x; 1.0065x over previous
#include <cuda_runtime.h>
#include <cstdint>

// Problem shape (fixed by the dataset instance)
#define BB   2
#define HH   32
#define SS   4096
#define DD   128
#define BLK  512
#define NB   (SS / BLK)          // 8
#define NCTA (BB * HH * NB)      // 512
#define NT   256
#define EPS_F 1e-6f

// Smem strides chosen for conflict-free mma fragment loads:
//  A-fragment loads (stride SPAD=132): bank = (4g + t) -> 32 distinct
//  B-fragment loads (stride VPAD=136): bank = (8t + g) -> 32 distinct
#define SPAD 132
#define VPAD 136

// Shared layout (floats):
//  Sdm  : 128 x VPAD, cols 0..127 = S_dm, col 128 = Z (fused den operand)
//  stage: phase1 = 2 double-buffered (16xSPAD phiK + 16xVPAD V); phase2 = 64xSPAD phiQ
//  den  : 64
#define BUF_FLOATS  (16 * SPAD + 16 * VPAD)       // 4288
#define STAGE_OFF   (DD * VPAD)                   // 17408
#define DEN_OFF     (STAGE_OFF + 2 * BUF_FLOATS)  // 25984
#define SMEM_FLOATS (DEN_OFF + 64)                // 26048
#define SMEM_BYTES  (SMEM_FLOATS * 4)             // 104192 -> 2 CTAs/SM

__device__ __forceinline__ float phi_elu1(float y) {
    return y > 0.0f ? y + 1.0f : __expf(y);
}

__device__ __forceinline__ uint32_t f2tf(float x) {
    uint32_t u;
    asm("cvt.rna.tf32.f32 %0, %1;" : "=r"(u) : "f"(x));
    return u;
}

__device__ __forceinline__ void mma_tf32(float* c, const uint32_t* a, const uint32_t* b) {
    asm volatile(
        "mma.sync.aligned.m16n8k8.row.col.f32.tf32.tf32.f32 "
        "{%0,%1,%2,%3}, {%4,%5,%6,%7}, {%8,%9}, {%0,%1,%2,%3};\n"
        : "+f"(c[0]), "+f"(c[1]), "+f"(c[2]), "+f"(c[3])
        : "r"(a[0]), "r"(a[1]), "r"(a[2]), "r"(a[3]), "r"(b[0]), "r"(b[1]));
}

extern "C" __global__ void __launch_bounds__(NT, 2)
lin_attn_tc2(const float* __restrict__ q,
             const float* __restrict__ k,
             const float* __restrict__ v,
             const float* __restrict__ sc,
             const float* __restrict__ bi,
             float* __restrict__ out)
{
    extern __shared__ float sm[];
    float* Sdm   = sm;                 // [128][VPAD]
    float* stage = sm + STAGE_OFF;
    float* den   = sm + DEN_OFF;

    const int tid  = threadIdx.x;
    const int lane = tid & 31;
    const int w    = tid >> 5;          // warp 0..7
    const int g    = lane >> 2;         // 0..7
    const int t    = lane & 3;          // 0..3

    const int c  = blockIdx.x;
    const int n  = c % NB;
    const int bh = c / NB;
    const int h  = bh % HH;
    const long base = ((long)bh * SS + (long)n * BLK) * DD;

    const float* qb = q + base;
    const float* kb = k + base;
    const float* vb = v + base;
    float*       ob = out + base;

    const int lrow = w;                 // loader row 0..7
    const int c4   = lane * 4;          // loader column group
    const float4 sc4 = *(const float4*)(sc + h * DD + c4);
    const float4 bi4 = *(const float4*)(bi + h * DD + c4);

    // ================= Phase 1: S_dm = phi(K)^T V ; Z = sum phi(K) ==========
    // warp tiling: wd in {0,1} -> 64 d-rows; wm1 in {0..3} -> 32 m-cols
    const int wd  = w & 1;
    const int wm1 = w >> 1;

    float acc[4][4][4];
    #pragma unroll
    for (int a = 0; a < 4; ++a)
        #pragma unroll
        for (int b = 0; b < 4; ++b)
            #pragma unroll
            for (int r = 0; r < 4; ++r) acc[a][b][r] = 0.0f;

    float4 zacc = make_float4(0.f, 0.f, 0.f, 0.f);
    float4 kv[2], vv[2];

#define LOADCH(ch) do {                                                     \
        const float* kc_ = kb + (long)(ch) * 16 * DD;                       \
        const float* vc_ = vb + (long)(ch) * 16 * DD;                       \
        kv[0] = *(const float4*)(kc_ + (long)lrow * DD + c4);               \
        kv[1] = *(const float4*)(kc_ + (long)(lrow + 8) * DD + c4);         \
        vv[0] = *(const float4*)(vc_ + (long)lrow * DD + c4);               \
        vv[1] = *(const float4*)(vc_ + (long)(lrow + 8) * DD + c4);         \
    } while (0)

#define STORECH(pk_, pv_) do {                                              \
        _Pragma("unroll")                                                   \
        for (int j_ = 0; j_ < 2; ++j_) {                                    \
            const int r_ = lrow + 8 * j_;                                   \
            float4 p_;                                                      \
            p_.x = phi_elu1(fmaf(kv[j_].x, sc4.x, bi4.x));                  \
            p_.y = phi_elu1(fmaf(kv[j_].y, sc4.y, bi4.y));                  \
            p_.z = phi_elu1(fmaf(kv[j_].z, sc4.z, bi4.z));                  \
            p_.w = phi_elu1(fmaf(kv[j_].w, sc4.w, bi4.w));                  \
            zacc.x += p_.x; zacc.y += p_.y; zacc.z += p_.z; zacc.w += p_.w; \
            uint4 pu_ = make_uint4(f2tf(p_.x), f2tf(p_.y),                  \
                                   f2tf(p_.z), f2tf(p_.w));                 \
            *(uint4*)((pk_) + r_ * SPAD + c4) = pu_;                        \
            uint4 vu_ = make_uint4(f2tf(vv[j_].x), f2tf(vv[j_].y),          \
                                   f2tf(vv[j_].z), f2tf(vv[j_].w));         \
            *(uint4*)((pv_) + r_ * VPAD + c4) = vu_;                        \
        }                                                                   \
    } while (0)

    // prologue: chunk 0 -> buf0, prefetch chunk 1
    LOADCH(0);
    STORECH(stage, stage + 16 * SPAD);
    LOADCH(1);
    __syncthreads();

    for (int ch = 0; ch < BLK / 16; ++ch) {
        const int p = ch & 1;
        float* pk = stage + p * BUF_FLOATS;
        float* pv = pk + 16 * SPAD;

        // pipeline: store chunk ch+1 into alternate buffer, prefetch ch+2
        if (ch < BLK / 16 - 1) {
            float* npk = stage + (p ^ 1) * BUF_FLOATS;
            STORECH(npk, npk + 16 * SPAD);
        }
        if (ch < BLK / 16 - 2) LOADCH(ch + 2);

        // mma on buffer p: 2 k-steps of 8 over 16 staged s-rows
        #pragma unroll
        for (int ks = 0; ks < 2; ++ks) {
            const int sb = ks * 8;
            uint32_t B[4][2];
            #pragma unroll
            for (int mt = 0; mt < 4; ++mt) {
                const int m = wm1 * 32 + mt * 8 + g;
                B[mt][0] = __float_as_uint(pv[(sb + t) * VPAD + m]);
                B[mt][1] = __float_as_uint(pv[(sb + t + 4) * VPAD + m]);
            }
            #pragma unroll
            for (int dt = 0; dt < 4; ++dt) {
                const int d0 = wd * 64 + dt * 16;
                uint32_t A[4];
                A[0] = __float_as_uint(pk[(sb + t)     * SPAD + d0 + g]);
                A[1] = __float_as_uint(pk[(sb + t)     * SPAD + d0 + g + 8]);
                A[2] = __float_as_uint(pk[(sb + t + 4) * SPAD + d0 + g]);
                A[3] = __float_as_uint(pk[(sb + t + 4) * SPAD + d0 + g + 8]);
                #pragma unroll
                for (int mt = 0; mt < 4; ++mt)
                    mma_tf32(acc[dt][mt], A, B[mt]);
            }
        }
        __syncthreads();
    }

    // write S_dm to smem
    #pragma unroll
    for (int dt = 0; dt < 4; ++dt) {
        const int d0 = wd * 64 + dt * 16;
        #pragma unroll
        for (int mt = 0; mt < 4; ++mt) {
            const int m = wm1 * 32 + mt * 8 + 2 * t;
            *(float2*)(Sdm + (d0 + g)     * VPAD + m) = make_float2(acc[dt][mt][0], acc[dt][mt][1]);
            *(float2*)(Sdm + (d0 + g + 8) * VPAD + m) = make_float2(acc[dt][mt][2], acc[dt][mt][3]);
        }
    }

    // prefetch Q chunk 0 (overlaps Z reduction)
    float4 qreg[8];
    #pragma unroll
    for (int j = 0; j < 8; ++j)
        qreg[j] = *(const float4*)(qb + (long)(lrow + 8 * j) * DD + c4);

    // reduce Z into Sdm column 128 (cols 129..135 zeroed)
    *(float4*)(stage + lrow * DD + c4) = zacc;
    __syncthreads();
    if (tid < DD) {
        float s = 0.0f;
        #pragma unroll
        for (int r = 0; r < 8; ++r) s += stage[r * DD + tid];
        *(float4*)(Sdm + tid * VPAD + 128) = make_float4(s, 0.f, 0.f, 0.f);
        *(float4*)(Sdm + tid * VPAD + 132) = make_float4(0.f, 0.f, 0.f, 0.f);
    }
    __syncthreads();

    // ===== Phase 2: out = phi(Q) [S_dm | Z] ; den fused as column 128 ======
    // chunk = 64 s-rows; warp grid 2s x 4m: tile 32s x 32m
    const int ws = w & 1;
    const int wm = w >> 1;
    const int s0 = ws * 32;
    const int m0 = wm * 32;

    for (int chq = 0; chq < BLK / 64; ++chq) {
        // stage phi(Q) as tf32 (64 rows x SPAD)
        #pragma unroll
        for (int j = 0; j < 8; ++j) {
            const int r = lrow + 8 * j;
            float4 p;
            p.x = phi_elu1(fmaf(qreg[j].x, sc4.x, bi4.x));
            p.y = phi_elu1(fmaf(qreg[j].y, sc4.y, bi4.y));
            p.z = phi_elu1(fmaf(qreg[j].z, sc4.z, bi4.z));
            p.w = phi_elu1(fmaf(qreg[j].w, sc4.w, bi4.w));
            uint4 pu = make_uint4(f2tf(p.x), f2tf(p.y), f2tf(p.z), f2tf(p.w));
            *(uint4*)(stage + r * SPAD + c4) = pu;
        }
        __syncthreads();

        // prefetch next Q chunk (overlaps mma)
        if (chq < BLK / 64 - 1) {
            const float* qc = qb + (long)(chq + 1) * 64 * DD;
            #pragma unroll
            for (int j = 0; j < 8; ++j)
                qreg[j] = *(const float4*)(qc + (long)(lrow + 8 * j) * DD + c4);
        }

        // GEMM: warp computes 32(s) x 32(m) (+ Z column for wm==0), K = 128
        float accq[2][5][4];
        #pragma unroll
        for (int st = 0; st < 2; ++st)
            #pragma unroll
            for (int mt = 0; mt < 5; ++mt)
                #pragma unroll
                for (int r = 0; r < 4; ++r) accq[st][mt][r] = 0.0f;

        #pragma unroll
        for (int kk = 0; kk < DD / 8; ++kk) {
            const int kb8 = kk * 8;
            uint32_t A[2][4];
            #pragma unroll
            for (int st = 0; st < 2; ++st) {
                const int row = s0 + st * 16;
                A[st][0] = __float_as_uint(stage[(row + g)     * SPAD + kb8 + t]);
                A[st][1] = __float_as_uint(stage[(row + g + 8) * SPAD + kb8 + t]);
                A[st][2] = __float_as_uint(stage[(row + g)     * SPAD + kb8 + t + 4]);
                A[st][3] = __float_as_uint(stage[(row + g + 8) * SPAD + kb8 + t + 4]);
            }
            #pragma unroll
            for (int mt = 0; mt < 4; ++mt) {
                const int m = m0 + mt * 8 + g;
                uint32_t B[2];
                B[0] = __float_as_uint(Sdm[(kb8 + t)     * VPAD + m]);
                B[1] = __float_as_uint(Sdm[(kb8 + t + 4) * VPAD + m]);
                mma_tf32(accq[0][mt], A[0], B);
                mma_tf32(accq[1][mt], A[1], B);
            }
            if (wm == 0) {
                const int m = 128 + g;      // Z column tile
                uint32_t B[2];
                B[0] = __float_as_uint(Sdm[(kb8 + t)     * VPAD + m]);
                B[1] = __float_as_uint(Sdm[(kb8 + t + 4) * VPAD + m]);
                mma_tf32(accq[0][4], A[0], B);
                mma_tf32(accq[1][4], A[1], B);
            }
        }

        // den = Z-column result (col 128 -> n=0 of tile 4 -> lanes t==0, c0/c2)
        if (wm == 0 && t == 0) {
            #pragma unroll
            for (int st = 0; st < 2; ++st) {
                den[s0 + st * 16 + g]     = accq[st][4][0] + EPS_F;
                den[s0 + st * 16 + g + 8] = accq[st][4][2] + EPS_F;
            }
        }
        __syncthreads();   // den visible; stage reads complete

        // epilogue: scale by 1/den, store
        #pragma unroll
        for (int st = 0; st < 2; ++st) {
            const int rr   = s0 + st * 16 + g;
            const int r0   = chq * 64 + rr;
            const float i0 = 1.0f / den[rr];
            const float i1 = 1.0f / den[rr + 8];
            #pragma unroll
            for (int mt = 0; mt < 4; ++mt) {
                const int m = m0 + mt * 8 + 2 * t;
                *(float2*)(ob + (long)r0 * DD + m) =
                    make_float2(accq[st][mt][0] * i0, accq[st][mt][1] * i0);
                *(float2*)(ob + (long)(r0 + 8) * DD + m) =
                    make_float2(accq[st][mt][2] * i1, accq[st][mt][3] * i1);
            }
        }
    }
}

extern "C" void kernel_launch(void* const* d_in, const int* in_sizes, int n_in,
                              void* d_out, int out_size) {
    const float* q  = (const float*)d_in[0];
    const float* k  = (const float*)d_in[1];
    const float* v  = (const float*)d_in[2];
    const float* sc = (const float*)d_in[3];
    const float* bi = (const float*)d_in[4];
    float* out = (float*)d_out;

    cudaFuncSetAttribute(lin_attn_tc2,
                         cudaFuncAttributeMaxDynamicSharedMemorySize, SMEM_BYTES);
    lin_attn_tc2<<<NCTA, NT, SMEM_BYTES>>>(q, k, v, sc, bi, out);
}